// round 13
// baseline (speedup 1.0000x reference)
#include <cuda_runtime.h>

// FasterTensorProduct — single-launch producer/consumer.
// out[b,n1,n2,k] = sum_c sh[b,n1,c] * Y[b,n2][k][c],  Y = x @ A_c (weight-derived).
// Blocks 0..511 produce Y rows and release per-row flags; blocks 512..2687 run
// the proven stage-2 store loop, spin-waiting on the flag for their n2 row.

#define IN_DIM 272
#define NROW   512   // B*N
#define NB     4
#define NN     128

#define W0E_OFF 0      // 96 x 64
#define W1O_OFF 6144   // 128 x 32
#define W1E_OFF 10240  // 80 x 32
#define W0O_OFF 12800  // 48 x 16

#define T1 8
#define NCONS 2176           // 34 * 16 * 4
#define NBLOCKS (NROW + NCONS)

// Y scratch: [row][k] float4 (c innermost). 2.23 MB, L2-resident.
__device__ float4 g_Y[NROW * IN_DIM];
__device__ int    g_flag[NROW];

__global__ __launch_bounds__(256, 6) void tp_fused(const float* __restrict__ in_,
                                                   const float* __restrict__ sh,
                                                   const float* __restrict__ w,
                                                   float* __restrict__ out)
{
    const int bid = blockIdx.x;

    if (bid < NROW) {
        // ================= producer: one Y row =================
        __shared__ float sx[IN_DIM];
        const int r0 = bid;
        const int t  = threadIdx.x;

        for (int idx = t; idx < IN_DIM; idx += 256)   // FIX: 272 > 256, must loop
            sx[idx] = in_[r0 * IN_DIM + idx];
        __syncthreads();

        if (t < 64) {
            // segment A: o = t
            const int o = t;
            float a0 = 0.f, a1[3] = {};
            #pragma unroll 8
            for (int j = 0; j < 64; j++)
                a0 += sx[j] * w[W0E_OFF + j * 64 + o];
            #pragma unroll 4
            for (int k = 0; k < 32; k++) {
                const float wv = w[W0E_OFF + (64 + k) * 64 + o];
                #pragma unroll
                for (int d = 0; d < 3; d++) a1[d] += sx[64 + 3 * k + d] * wv;
            }
            const float s  = 0.10206207262f;   // 1/sqrt(96)
            const float s3 = 0.05892556510f;   // 1/sqrt(96*3)
            g_Y[r0 * IN_DIM + o] = make_float4(s * a0, s3 * a1[0], s3 * a1[1], s3 * a1[2]);
        }
        else if (t < 96) {
            // segment B: o = t-64
            const int o = t - 64;
            float b0 = 0.f, b1[3] = {}, b2[3] = {};
            #pragma unroll 8
            for (int j = 0; j < 64; j++)
                b0 += sx[j] * w[W1O_OFF + j * 32 + o];
            #pragma unroll 4
            for (int k = 0; k < 32; k++) {
                const float wv = w[W1O_OFF + (64 + k) * 32 + o];
                #pragma unroll
                for (int d = 0; d < 3; d++) b1[d] += sx[64 + 3 * k + d] * wv;
            }
            #pragma unroll 4
            for (int k = 0; k < 32; k++) {
                const float wv = w[W1O_OFF + (96 + k) * 32 + o];
                #pragma unroll
                for (int e = 0; e < 3; e++) b2[e] += sx[160 + 3 * k + e] * wv;
            }
            const float s   = 0.08838834765f;  // 1/sqrt(128)
            const float si2 = 0.0625f;         // 1/sqrt(256)
            #pragma unroll
            for (int c = 0; c < 3; c++) {
                float v[4];
                v[0]               =  s   * b1[c];
                v[1 + c]           =  s   * b0;
                v[1 + (c + 2) % 3] =  si2 * b2[(c + 1) % 3];
                v[1 + (c + 1) % 3] = -si2 * b2[(c + 2) % 3];
                g_Y[r0 * IN_DIM + 64 + 3 * o + c] = make_float4(v[0], v[1], v[2], v[3]);
            }
        }
        else if (t < 128) {
            // segment C: o = t-96
            const int o = t - 96;
            float c0[3] = {}, c1[3] = {}, c2 = 0.f;
            #pragma unroll 4
            for (int k = 0; k < 32; k++) {
                const float wv = w[W1E_OFF + k * 32 + o];
                #pragma unroll
                for (int e = 0; e < 3; e++) c0[e] += sx[64 + 3 * k + e] * wv;
            }
            #pragma unroll 4
            for (int k = 0; k < 32; k++) {
                const float wv = w[W1E_OFF + (32 + k) * 32 + o];
                #pragma unroll
                for (int d = 0; d < 3; d++) c1[d] += sx[160 + 3 * k + d] * wv;
            }
            #pragma unroll 8
            for (int j = 0; j < 16; j++)
                c2 += sx[256 + j] * w[W1E_OFF + (64 + j) * 32 + o];
            const float s   = 0.11180339887f;  // 1/sqrt(80)
            const float si2 = 0.07905694150f;  // 1/sqrt(160)
            #pragma unroll
            for (int c = 0; c < 3; c++) {
                float v[4];
                v[0]               =  s   * c1[c];
                v[1 + c]           =  s   * c2;
                v[1 + (c + 2) % 3] =  si2 * c0[(c + 1) % 3];
                v[1 + (c + 1) % 3] = -si2 * c0[(c + 2) % 3];
                g_Y[r0 * IN_DIM + 160 + 3 * o + c] = make_float4(v[0], v[1], v[2], v[3]);
            }
        }
        else if (t < 144) {
            // segment D: o = t-128
            const int o = t - 128;
            float d0[3] = {}, d1 = 0.f;
            #pragma unroll 4
            for (int k = 0; k < 32; k++) {
                const float wv = w[W0O_OFF + k * 16 + o];
                #pragma unroll
                for (int d = 0; d < 3; d++) d0[d] += sx[160 + 3 * k + d] * wv;
            }
            #pragma unroll 8
            for (int j = 0; j < 16; j++)
                d1 += sx[256 + j] * w[W0O_OFF + (32 + j) * 16 + o];
            const float s  = 0.14433756730f;   // 1/sqrt(48)
            const float s3 = 0.08333333333f;   // 1/12
            g_Y[r0 * IN_DIM + 256 + o] = make_float4(s * d1, s3 * d0[0], s3 * d0[1], s3 * d0[2]);
        }
        __syncthreads();

        if (threadIdx.x == 0) {
            __threadfence();                  // make Y row globally visible
            atomicExch(&g_flag[r0], 1);       // release
        }
    }
    else {
        // ================= consumer: stage-2 store loop =================
        const int cid = bid - NROW;
        const int b   = cid / (34 * 16);
        const int rem = cid - b * (34 * 16);
        const int n1t = rem / 34;
        const int bx  = rem - n1t * 34;

        __shared__ float4 ssh[T1];
        const int tid = threadIdx.x;
        const int n1b = n1t * T1;
        const int j   = bx * 256 + tid;       // n2*68 + kv, 0..8703

        if (tid < T1)
            ssh[tid] = reinterpret_cast<const float4*>(sh)[b * NN + n1b + tid];

        const int n2  = j / 68;
        const int kv  = j - n2 * 68;
        const int row = b * NN + n2;

        // wait for this row's producer
        {
            const volatile int* fp = &g_flag[row];
            while (*fp == 0) __nanosleep(64);
        }
        __threadfence();                      // acquire: order Y loads after flag
        __syncthreads();                      // ssh visible

        const float4* Yp = &g_Y[row * IN_DIM + kv * 4];
        const float4 y0 = Yp[0], y1 = Yp[1], y2 = Yp[2], y3 = Yp[3];

        float4* op = reinterpret_cast<float4*>(out)
                   + (size_t)(b * NN + n1b) * (NN * (IN_DIM / 4)) + j;
        const size_t stride = NN * (IN_DIM / 4);  // 8704 float4 per n1

        #pragma unroll
        for (int i = 0; i < T1; i++) {
            const float4 s = ssh[i];
            float4 o;
            o.x = s.x * y0.x + s.y * y0.y + s.z * y0.z + s.w * y0.w;
            o.y = s.x * y1.x + s.y * y1.y + s.z * y1.z + s.w * y1.w;
            o.z = s.x * y2.x + s.y * y2.y + s.z * y2.z + s.w * y2.w;
            o.w = s.x * y3.x + s.y * y3.y + s.z * y3.z + s.w * y3.w;
            op[i * stride] = o;
        }
    }
}

extern "C" void kernel_launch(void* const* d_in, const int* in_sizes, int n_in,
                              void* d_out, int out_size)
{
    const float* in_ = (const float*)d_in[0];   // (4,1,128,272)
    const float* sh  = (const float*)d_in[1];   // (4,128,1,4)
    const float* w   = (const float*)d_in[2];   // (13568,)
    float* out = (float*)d_out;

    void* flagAddr = nullptr;
    cudaGetSymbolAddress(&flagAddr, g_flag);
    cudaMemsetAsync(flagAddr, 0, NROW * sizeof(int), 0);

    tp_fused<<<NBLOCKS, 256>>>(in_, sh, w, out);
}